// round 10
// baseline (speedup 1.0000x reference)
#include <cuda_runtime.h>

// UpsampleLayer2D: x[B,R,C,64] -> out[B,2R,2C,16]
// out[b, ro, co, c] = x[b, ro%R, co%C, 4c + q],  q = 2*(ro>=R) + (co>=C)
//
// R10: champion warp-level layout, block size 512 (middle of the 256/1024
// axis: R8 ncu-best, R9 harness-best). Per-thread code identical to R8/R9.
//   read : warp = 2KB fully contiguous, sector-perfect (4x LDG.128/thread)
//   write: per quadrant one lane-contiguous STG.128; block = four 2KB
//          contiguous quadrant streams, full 128B lines covered (no RFO).
// Measured ceiling: ~83% dram__cycles_active / 6.6 TB/s on 655MB single-touch
// traffic. All structural deviations (v8 ops, half-pixel threads, fat blocks,
// persistence, cache hints) tested R2-R9 and regressed or were neutral.

#define B_  32
#define R_  200
#define C_  200
#define NPIX    (B_ * R_ * C_)       // 1,280,000
#define NGROUPS (NPIX * 4)           // 5,120,000 (pixel,role) items
#define TPB     512
#define GRID    (NGROUPS / TPB)      // 10000, exact

__device__ __forceinline__ float comp(const float4& v, int q) {
    switch (q) {
        case 0:  return v.x;
        case 1:  return v.y;
        case 2:  return v.z;
        default: return v.w;
    }
}

__global__ __launch_bounds__(TPB)
void upsample_kernel(const float* __restrict__ in, float* __restrict__ out) {
    const unsigned idx = blockIdx.x * TPB + threadIdx.x;   // < NGROUPS, exact

    const unsigned t   = idx & 3u;      // role: input channels [16t, 16t+16)
    const unsigned pix = idx >> 2;

    const unsigned col = pix % C_;
    const unsigned tmp = pix / C_;
    const unsigned row = tmp % R_;
    const unsigned b   = tmp / R_;

    // Contiguous 64B read: channels [16t, 16t+16), front-batched.
    const float4* ip = reinterpret_cast<const float4*>(in) + pix * 16u + t * 4u;
    float4 v0 = ip[0];
    float4 v1 = ip[1];
    float4 v2 = ip[2];
    float4 v3 = ip[3];

    float4* op = reinterpret_cast<float4*>(out);

    #pragma unroll
    for (int q = 0; q < 4; q++) {
        const unsigned ro = row + R_ * (q >> 1);
        const unsigned co = col + C_ * (q & 1);
        const unsigned obase = ((b * (2u * R_) + ro) * (2u * C_) + co) * 4u + t;
        float4 w;
        w.x = comp(v0, q);
        w.y = comp(v1, q);
        w.z = comp(v2, q);
        w.w = comp(v3, q);
        op[obase] = w;
    }
}

extern "C" void kernel_launch(void* const* d_in, const int* in_sizes, int n_in,
                              void* d_out, int out_size) {
    const float* x = (const float*)d_in[0];
    float* out = (float*)d_out;
    upsample_kernel<<<GRID, TPB>>>(x, out);
}

// round 11
// speedup vs baseline: 1.0179x; 1.0179x over previous
#include <cuda_runtime.h>

// UpsampleLayer2D: x[B,R,C,64] -> out[B,2R,2C,16]
// out[b, ro, co, c] = x[b, ro%R, co%C, 4c + q],  q = 2*(ro>=R) + (co>=C)
//
// FINAL (= R9, harness-best 97.92us): champion warp-level layout, TPB=1024.
// 4 threads per input pixel (role t):
//   read : channels [16t,16t+16) as 4 front-batched LDG.128
//          -> warp reads 2KB fully contiguous, sector-perfect.
//   write: per quadrant one lane-contiguous STG.128 -> warp writes 512B
//          contiguous per quadrant stream, full 128B lines covered (no RFO).
//
// Measured ceiling for this pure 655MB single-touch permutation:
// ~83% dram__cycles_active / 6.6 TB/s. Axes exhaustively probed R2-R10:
// MLP, occupancy, 256-bit ops, lane layout, block shape/size, persistence,
// cache hints — all neutral or regressions. No traffic reduction exists
// (zero reuse, zero compute); kernel is memory-system-pinned.

#define B_  32
#define R_  200
#define C_  200
#define NPIX    (B_ * R_ * C_)       // 1,280,000
#define NGROUPS (NPIX * 4)           // 5,120,000 (pixel,role) items
#define TPB     1024
#define GRID    (NGROUPS / TPB)      // 5000, exact

__device__ __forceinline__ float comp(const float4& v, int q) {
    switch (q) {
        case 0:  return v.x;
        case 1:  return v.y;
        case 2:  return v.z;
        default: return v.w;
    }
}

__global__ __launch_bounds__(TPB)
void upsample_kernel(const float* __restrict__ in, float* __restrict__ out) {
    const unsigned idx = blockIdx.x * TPB + threadIdx.x;   // < NGROUPS, exact

    const unsigned t   = idx & 3u;      // role: input channels [16t, 16t+16)
    const unsigned pix = idx >> 2;

    const unsigned col = pix % C_;
    const unsigned tmp = pix / C_;
    const unsigned row = tmp % R_;
    const unsigned b   = tmp / R_;

    // Contiguous 64B read: channels [16t, 16t+16), front-batched.
    const float4* ip = reinterpret_cast<const float4*>(in) + pix * 16u + t * 4u;
    float4 v0 = ip[0];
    float4 v1 = ip[1];
    float4 v2 = ip[2];
    float4 v3 = ip[3];

    float4* op = reinterpret_cast<float4*>(out);

    #pragma unroll
    for (int q = 0; q < 4; q++) {
        const unsigned ro = row + R_ * (q >> 1);
        const unsigned co = col + C_ * (q & 1);
        const unsigned obase = ((b * (2u * R_) + ro) * (2u * C_) + co) * 4u + t;
        float4 w;
        w.x = comp(v0, q);
        w.y = comp(v1, q);
        w.z = comp(v2, q);
        w.w = comp(v3, q);
        op[obase] = w;
    }
}

extern "C" void kernel_launch(void* const* d_in, const int* in_sizes, int n_in,
                              void* d_out, int out_size) {
    const float* x = (const float*)d_in[0];
    float* out = (float*)d_out;
    upsample_kernel<<<GRID, TPB>>>(x, out);
}